// round 11
// baseline (speedup 1.0000x reference)
#include <cuda_runtime.h>
#include <cuda_fp16.h>
#include <math.h>
#include <stdint.h>

// ---------------- problem constants ----------------
#define N_NODES   20000
#define N_PAD     20096                 // 157 * 128
#define N_EDGES   320000
#define TOT_E     (N_EDGES + N_NODES)   // + self loops
#define F_INDIM   22
#define C_DIM     64
#define H_HEADS   4
#define HC        256
#define NLR       512                   // fused xl|xr row width
#define G_GRAPHS  20
#define NODES_PG  1000
#define OUT_DIM   128
#define NEG_SLOPE 0.2f

#define NBLK_SCAN 79                    // ceil(20000/256)

// split point: 79 M-tiles = 10112 nodes
#define SPLIT_TILES 79
#define SPLIT_NODES (SPLIT_TILES * 128) // 10112
#define EA_BLOCKS (SPLIT_NODES / 8)              // 1264 (8 warps/block)
#define EB_NODES  (N_NODES - SPLIT_NODES)        // 9888
#define EB_BLOCKS ((EB_NODES + 7) / 8)           // 1236

// ---------------- scratch (static device globals; no allocation) ----------------
__device__ __half g_hA[N_PAD * HC];
__device__ __half g_hB[N_PAD * HC];
__device__ __half g_xlr[N_PAD * NLR];       // [node][xl(256) | xr(256)]
__device__ __half g_Wt0[NLR * C_DIM];       // layer0 weights, [n][k] fp16
__device__ __half g_Wt1[NLR * HC];
__device__ __half g_Wt2[NLR * HC];
__device__ float  g_xg[G_GRAPHS * 2 * HC];
__device__ float  g_poolP[G_GRAPHS * 8 * 2 * HC];
__device__ int    g_cnt[N_NODES];
__device__ int    g_rowptr[N_NODES + 1];
__device__ int    g_fill[N_NODES];
__device__ int    g_col[TOT_E];
__device__ int    g_part[128];              // decoupled-lookback state

// ---------------- helpers ----------------
__device__ __forceinline__ uint32_t smem_u32(const void* p) {
    uint32_t a;
    asm("{ .reg .u64 t; cvta.to.shared.u64 t, %1; cvt.u32.u64 %0, t; }"
        : "=r"(a) : "l"(p));
    return a;
}
__device__ __forceinline__ void cp_async16(uint32_t saddr, const void* gaddr) {
    asm volatile("cp.async.cg.shared.global [%0], [%1], 16;"
                 :: "r"(saddr), "l"(gaddr));
}
__device__ __forceinline__ void cp_commit() {
    asm volatile("cp.async.commit_group;" ::: "memory");
}
template <int NN>
__device__ __forceinline__ void cp_wait() {
    asm volatile("cp.async.wait_group %0;" :: "n"(NN) : "memory");
}

// ---------------- main-path prologue: Wt0 prep + input projection ----------
#define PREP0_BLOCKS 128                    // 32768 / 256
#define PROJ_BLOCKS  5000
#define INIT_BLOCKS  (PREP0_BLOCKS + PROJ_BLOCKS)
#define L0_ELEMS (NLR * C_DIM)              // 32768
#define L12_ELEMS (NLR * HC)                // 131072

__global__ void fused_init_kernel(const float* __restrict__ x,
                                  const float* __restrict__ Win,
                                  const float* __restrict__ bin,
                                  const float* __restrict__ Wl0,
                                  const float* __restrict__ Wr0) {
    int b = blockIdx.x, t = threadIdx.x;
    if (b < PREP0_BLOCKS) {
        int idx = b * 256 + t;              // < 32768
        int n = idx / C_DIM, k = idx - n * C_DIM;
        float v = (n < HC) ? Wl0[k * HC + n] : Wr0[k * HC + (n - HC)];
        g_Wt0[idx] = __float2half(v);
    } else {
        int nb = b - PREP0_BLOCKS;
        int ty = t >> 6, c = t & 63;
        int node = nb * 4 + ty;
        __shared__ float xs[4][F_INDIM];
        if (c < F_INDIM) xs[ty][c] = x[node * F_INDIM + c];
        __syncthreads();
        float acc = bin[c];
#pragma unroll
        for (int k = 0; k < F_INDIM; k++)
            acc = fmaf(xs[ty][k], Win[k * C_DIM + c], acc);
        g_hA[node * C_DIM + c] = __float2half(fmaxf(acc, 0.f));
    }
}

// ---------------- side-stream: Wt1/Wt2 prep ----------------
__global__ void prep12_kernel(const float* __restrict__ Wl1, const float* __restrict__ Wr1,
                              const float* __restrict__ Wl2, const float* __restrict__ Wr2) {
    int idx = blockIdx.x * 256 + threadIdx.x;     // 2 * 131072
    const float* Wl; const float* Wr; __half* Wt; int r;
    if (idx < L12_ELEMS) { Wl = Wl1; Wr = Wr1; Wt = g_Wt1; r = idx; }
    else                 { Wl = Wl2; Wr = Wr2; Wt = g_Wt2; r = idx - L12_ELEMS; }
    int n = r / HC, k = r - n * HC;
    float v = (n < HC) ? Wl[k * HC + n] : Wr[k * HC + (n - HC)];
    Wt[r] = __float2half(v);
}

// ---------------- CSR branch (side stream) ----------------
__global__ void initcnt_kernel() {
    int i = blockIdx.x * 256 + threadIdx.x;
    if (i < N_NODES) g_cnt[i] = 1;          // self loop pre-counted
    if (blockIdx.x == 0 && threadIdx.x < 128) g_part[threadIdx.x] = 0;
}

__global__ void hist_kernel(const int* __restrict__ dst) {
    int e4 = blockIdx.x * blockDim.x + threadIdx.x;
    if (e4 < N_EDGES / 4) {
        int4 d = ((const int4*)dst)[e4];
        atomicAdd(&g_cnt[d.x], 1);
        atomicAdd(&g_cnt[d.y], 1);
        atomicAdd(&g_cnt[d.z], 1);
        atomicAdd(&g_cnt[d.w], 1);
    }
}

#define AFLAG (1 << 30)
#define PFLAG (2 << 30)
#define VMASK 0x3FFFFFFF

__global__ void scanfill_kernel() {
    __shared__ int sh[256];
    __shared__ int s_prefix;
    int b = blockIdx.x, t = threadIdx.x;
    int i = b * 256 + t;
    int v = (i < N_NODES) ? g_cnt[i] : 0;
    sh[t] = v;
    __syncthreads();
#pragma unroll
    for (int off = 1; off < 256; off <<= 1) {
        int u = (t >= off) ? sh[t - off] : 0;
        __syncthreads();
        sh[t] += u;
        __syncthreads();
    }
    int total = sh[255];

    if (b == 0) {
        if (t == 0) {
            s_prefix = 0;
            atomicExch(&g_part[0], PFLAG | total);
        }
    } else {
        if (t == 0) atomicExch(&g_part[b], AFLAG | total);
        __syncwarp();
        if (t < 32) {
            int lane = t;
            int run = 0;
            int j = b - 1;
            for (;;) {
                int idx = j - lane;
                int sval = 0;
                if (idx >= 0) {
                    do { sval = atomicAdd(&g_part[idx], 0); } while (sval == 0);
                }
                unsigned pm = __ballot_sync(0xffffffffu, idx >= 0 && (sval & PFLAG));
                int contrib;
                bool done;
                if (pm) {
                    int lp = __ffs(pm) - 1;
                    contrib = (lane <= lp) ? (sval & VMASK) : 0;
                    done = true;
                } else {
                    contrib = (idx >= 0) ? (sval & VMASK) : 0;
                    done = false;
                }
#pragma unroll
                for (int o = 16; o; o >>= 1)
                    contrib += __shfl_down_sync(0xffffffffu, contrib, o);
                if (lane == 0) run += contrib;
                if (done) break;
                j -= 32;
            }
            if (lane == 0) {
                s_prefix = run;
                atomicExch(&g_part[b], PFLAG | ((run + total) & VMASK));
            }
        }
    }
    __syncthreads();

    int incl = s_prefix + sh[t];
    int excl = incl - v;
    if (i < N_NODES) {
        g_rowptr[i + 1] = incl;
        g_col[excl] = i;          // self loop first in row
        g_fill[i] = excl + 1;
    }
    if (i == 0) g_rowptr[0] = 0;
}

__global__ void scatter_kernel(const int* __restrict__ src,
                               const int* __restrict__ dst) {
    int e4 = blockIdx.x * blockDim.x + threadIdx.x;
    if (e4 < N_EDGES / 4) {
        int4 s = ((const int4*)src)[e4];
        int4 d = ((const int4*)dst)[e4];
        int p0 = atomicAdd(&g_fill[d.x], 1);
        int p1 = atomicAdd(&g_fill[d.y], 1);
        int p2 = atomicAdd(&g_fill[d.z], 1);
        int p3 = atomicAdd(&g_fill[d.w], 1);
        g_col[p0] = s.x;
        g_col[p1] = s.y;
        g_col[p2] = s.z;
        g_col[p3] = s.w;
    }
}

// ---------------- fp16 mma.sync GEMM, cp.async 4-stage, ldmatrix frags ------
// C[rows, 512] = A[rows, K] @ Wt^T, row tiles offset by ytile0.
#define GBM 128
#define GBN 128
#define GBK 32
#define PITCH 40
#define A_ST (GBM * PITCH)
#define B_ST (GBN * PITCH)
#define STAGE_HALFS (A_ST + B_ST)
#define STG 4
#define GEMM_SMEM (STG * STAGE_HALFS * 2)    // 81920 bytes

__global__ __launch_bounds__(256, 2)
void gemm_f16_kernel(const __half* __restrict__ A,
                     const __half* __restrict__ Wt,
                     __half* __restrict__ Cout, int K, int ytile0) {
    extern __shared__ __half smh[];
    const uint32_t sbase = smem_u32(smh);

    int tid = threadIdx.x;
    int lane = tid & 31, wid = tid >> 5;
    int warp_m = wid >> 2;
    int warp_n = wid & 3;
    int fr = lane >> 2, fk = lane & 3;

    int row0 = (ytile0 + blockIdx.y) * GBM;
    int col0 = blockIdx.x * GBN;

    const int nch = K / GBK;

    int aRow = warp_m * 64 + (lane & 15);
    int aColH = (lane >> 4) * 8;
    int bRow = warp_n * 32 + ((lane >> 4) * 8) + (lane & 7);
    int bColH = ((lane >> 3) & 1) * 8;

    auto issue = [&](int ch) {
        uint32_t sA = sbase + (uint32_t)(ch % STG) * (STAGE_HALFS * 2);
        uint32_t sB = sA + A_ST * 2;
        const __half* aG = A + (size_t)row0 * K + ch * GBK;
        const __half* bG = Wt + (size_t)col0 * K + ch * GBK;
#pragma unroll
        for (int i = 0; i < 2; i++) {
            int idx = tid + i * 256;
            int m = idx >> 2, q = idx & 3;
            cp_async16(sA + (uint32_t)(m * PITCH + q * 8) * 2,
                       aG + (size_t)m * K + q * 8);
        }
#pragma unroll
        for (int i = 0; i < 2; i++) {
            int idx = tid + i * 256;
            int n = idx >> 2, q = idx & 3;
            cp_async16(sB + (uint32_t)(n * PITCH + q * 8) * 2,
                       bG + (size_t)n * K + q * 8);
        }
        cp_commit();
    };

    for (int p = 0; p < STG - 1 && p < nch; p++) issue(p);

    float acc[4][4][4] = {};

    for (int ch = 0; ch < nch; ch++) {
        int rem = nch - 1 - ch;
        if (rem >= 2) cp_wait<2>(); else if (rem == 1) cp_wait<1>(); else cp_wait<0>();
        __syncthreads();
        if (ch + STG - 1 < nch) issue(ch + STG - 1);

        uint32_t stA = sbase + (uint32_t)(ch % STG) * (STAGE_HALFS * 2);
        uint32_t stB = stA + A_ST * 2;
#pragma unroll
        for (int ks = 0; ks < 2; ks++) {
            uint32_t af[4][4];
#pragma unroll
            for (int mt = 0; mt < 4; mt++) {
                uint32_t ad = stA + (uint32_t)((aRow + mt * 16) * PITCH + aColH + ks * 16) * 2;
                asm volatile(
                    "ldmatrix.sync.aligned.m8n8.x4.shared.b16 {%0,%1,%2,%3}, [%4];"
                    : "=r"(af[mt][0]), "=r"(af[mt][1]),
                      "=r"(af[mt][2]), "=r"(af[mt][3]) : "r"(ad));
            }
            uint32_t bf[4][2];
#pragma unroll
            for (int p = 0; p < 2; p++) {
                uint32_t bd = stB + (uint32_t)((bRow + p * 16) * PITCH + bColH + ks * 16) * 2;
                uint32_t r0, r1, r2, r3;
                asm volatile(
                    "ldmatrix.sync.aligned.m8n8.x4.shared.b16 {%0,%1,%2,%3}, [%4];"
                    : "=r"(r0), "=r"(r1), "=r"(r2), "=r"(r3) : "r"(bd));
                bf[2 * p][0] = r0; bf[2 * p][1] = r1;
                bf[2 * p + 1][0] = r2; bf[2 * p + 1][1] = r3;
            }
#pragma unroll
            for (int mt = 0; mt < 4; mt++)
#pragma unroll
                for (int nt = 0; nt < 4; nt++) {
                    float* c = acc[mt][nt];
                    asm volatile(
                        "mma.sync.aligned.m16n8k16.row.col.f32.f16.f16.f32 "
                        "{%0,%1,%2,%3}, {%4,%5,%6,%7}, {%8,%9}, {%0,%1,%2,%3};"
                        : "+f"(c[0]), "+f"(c[1]), "+f"(c[2]), "+f"(c[3])
                        : "r"(af[mt][0]), "r"(af[mt][1]), "r"(af[mt][2]),
                          "r"(af[mt][3]), "r"(bf[nt][0]), "r"(bf[nt][1]));
                }
        }
    }
    __syncthreads();

#pragma unroll
    for (int mt = 0; mt < 4; mt++) {
#pragma unroll
        for (int nt = 0; nt < 4; nt++) {
            int row = row0 + warp_m * 64 + mt * 16 + fr;
            int col = col0 + warp_n * 32 + nt * 8 + 2 * fk;
            float* c = acc[mt][nt];
            *(__half2*)&Cout[(size_t)row * NLR + col] = __floats2half2_rn(c[0], c[1]);
            *(__half2*)&Cout[(size_t)(row + 8) * NLR + col] = __floats2half2_rn(c[2], c[3]);
        }
    }
}

// ---------------- fused GATv2 edge kernel (warp per node, node-range split) --
__global__ void gat_edge_kernel(const __half* __restrict__ xlr,
                                const float* __restrict__ att,
                                const float* __restrict__ bias,
                                const __half* __restrict__ hprev,
                                __half* __restrict__ hout,
                                int residual, int nbase, int ncount) {
    int widx = (blockIdx.x * blockDim.x + threadIdx.x) >> 5;
    if (widx >= ncount) return;
    int gw = nbase + widx;
    int lane = threadIdx.x & 31;
    int cbase = lane * 8;

    float xr_r[8], att_r[8];
    {
        uint4 u = *(const uint4*)&xlr[(size_t)gw * NLR + HC + cbase];
        const __half2* hp = (const __half2*)&u;
#pragma unroll
        for (int j = 0; j < 4; j++) {
            float2 f = __half22float2(hp[j]);
            xr_r[2 * j] = f.x; xr_r[2 * j + 1] = f.y;
        }
        const float4* q = (const float4*)&att[cbase];
        float4 c = q[0], d = q[1];
        att_r[0]=c.x; att_r[1]=c.y; att_r[2]=c.z; att_r[3]=c.w;
        att_r[4]=d.x; att_r[5]=d.y; att_r[6]=d.z; att_r[7]=d.w;
    }

    int e0 = g_rowptr[gw];
    int e1 = g_rowptr[gw + 1];

    float m = -INFINITY, den = 0.f;
    float acc[8] = {0.f,0.f,0.f,0.f,0.f,0.f,0.f,0.f};

    for (int base = e0; base < e1; base += 4) {
        int lim = e1 - base; if (lim > 4) lim = 4;
        int idx[4];
        uint4 u[4];
#pragma unroll
        for (int d = 0; d < 4; d++)
            if (d < lim) idx[d] = g_col[base + d];
#pragma unroll
        for (int d = 0; d < 4; d++)
            if (d < lim) u[d] = *(const uint4*)&xlr[(size_t)idx[d] * NLR + cbase];

#pragma unroll
        for (int d = 0; d < 4; d++) {
            if (d >= lim) break;
            const __half2* hp = (const __half2*)&u[d];
            float xv[8];
#pragma unroll
            for (int j = 0; j < 4; j++) {
                float2 f = __half22float2(hp[j]);
                xv[2 * j] = f.x; xv[2 * j + 1] = f.y;
            }

            float partial = 0.f;
#pragma unroll
            for (int j = 0; j < 8; j++) {
                float t = xv[j] + xr_r[j];
                t = fmaxf(t, NEG_SLOPE * t);
                partial = fmaf(t, att_r[j], partial);
            }
            partial += __shfl_xor_sync(0xffffffffu, partial, 1);
            partial += __shfl_xor_sync(0xffffffffu, partial, 2);
            partial += __shfl_xor_sync(0xffffffffu, partial, 4);
            float logit = partial;

            float m_new = fmaxf(m, logit);
            float scale = __expf(m - m_new);
            float pxe = __expf(logit - m_new);
            den = den * scale + pxe;
#pragma unroll
            for (int j = 0; j < 8; j++)
                acc[j] = fmaf(acc[j], scale, pxe * xv[j]);
            m = m_new;
        }
    }

    float inv = 1.f / (den + 1e-16f);
#pragma unroll
    for (int j = 0; j < 8; j++) {
        float v = fmaf(acc[j], inv, bias[cbase + j]);
        v = (v > 0.f) ? v : (__expf(v) - 1.f);
        if (residual) v += __half2float(hprev[gw * HC + cbase + j]);
        hout[gw * HC + cbase + j] = __float2half(v);
    }
}

// ---------------- pooling: partial mean+max (graph-range split) + head ------
__global__ void pool1_kernel(const __half* __restrict__ h, int gbase) {
    int g = gbase + blockIdx.y, ch = blockIdx.x;
    int c = threadIdx.x;
    const __half* base = h + ((size_t)g * NODES_PG + ch * 125) * HC;
    float s = 0.f, mx = -INFINITY;
    for (int n = 0; n < 125; n++) {
        float v = __half2float(base[n * HC + c]);
        s += v;
        mx = fmaxf(mx, v);
    }
    float* out = &g_poolP[(size_t)(g * 8 + ch) * 2 * HC];
    out[c] = s;
    out[HC + c] = mx;
}

__global__ void pool2_head_kernel(const float* __restrict__ Wout,
                                  const float* __restrict__ bout,
                                  float* __restrict__ out) {
    __shared__ float xg[2 * HC];
    int g = blockIdx.x;
    int t = threadIdx.x;
    float s = 0.f, mx = -INFINITY;
    for (int ch = 0; ch < 8; ch++) {
        const float* in = &g_poolP[(size_t)(g * 8 + ch) * 2 * HC];
        s += in[t];
        mx = fmaxf(mx, in[HC + t]);
    }
    xg[t] = s * (1.f / NODES_PG);
    xg[HC + t] = mx;
    __syncthreads();
    if (t < OUT_DIM) {
        float acc = bout[t];
#pragma unroll 8
        for (int k = 0; k < 2 * HC; k++)
            acc = fmaf(xg[k], Wout[k * OUT_DIM + t], acc);
        out[g * OUT_DIM + t] = acc;
    }
}

// ---------------- launch ----------------
extern "C" void kernel_launch(void* const* d_in, const int* in_sizes, int n_in,
                              void* d_out, int out_size) {
    const float* x    = (const float*)d_in[0];
    const int*   ei   = (const int*)d_in[1];
    const float* Win  = (const float*)d_in[3];
    const float* bin  = (const float*)d_in[4];
    const float* Wout = (const float*)d_in[5];
    const float* bout = (const float*)d_in[6];
    const float* Wl[3] = { (const float*)d_in[7],  (const float*)d_in[11], (const float*)d_in[15] };
    const float* Wr[3] = { (const float*)d_in[8],  (const float*)d_in[12], (const float*)d_in[16] };
    const float* At[3] = { (const float*)d_in[9],  (const float*)d_in[13], (const float*)d_in[17] };
    const float* Bi[3] = { (const float*)d_in[10], (const float*)d_in[14], (const float*)d_in[18] };
    float* out = (float*)d_out;

    const int* src = ei;
    const int* dst = ei + N_EDGES;

    __half *hA, *hB, *xlr, *Wt0, *Wt1, *Wt2;
    cudaGetSymbolAddress((void**)&hA,  g_hA);
    cudaGetSymbolAddress((void**)&hB,  g_hB);
    cudaGetSymbolAddress((void**)&xlr, g_xlr);
    cudaGetSymbolAddress((void**)&Wt0, g_Wt0);
    cudaGetSymbolAddress((void**)&Wt1, g_Wt1);
    cudaGetSymbolAddress((void**)&Wt2, g_Wt2);

    cudaFuncSetAttribute(gemm_f16_kernel,
                         cudaFuncAttributeMaxDynamicSharedMemorySize, GEMM_SMEM);

    static cudaStream_t s2 = nullptr;
    static cudaEvent_t evFork = nullptr, evCsr = nullptr, evPrep = nullptr;
    static cudaEvent_t evE0a = nullptr, evG1a = nullptr, evE1a = nullptr;
    static cudaEvent_t evG2a = nullptr, evE2a = nullptr, evP1a = nullptr;
    if (!s2) {
        cudaStreamCreateWithFlags(&s2, cudaStreamNonBlocking);
        cudaEventCreateWithFlags(&evFork, cudaEventDisableTiming);
        cudaEventCreateWithFlags(&evCsr,  cudaEventDisableTiming);
        cudaEventCreateWithFlags(&evPrep, cudaEventDisableTiming);
        cudaEventCreateWithFlags(&evE0a,  cudaEventDisableTiming);
        cudaEventCreateWithFlags(&evG1a,  cudaEventDisableTiming);
        cudaEventCreateWithFlags(&evE1a,  cudaEventDisableTiming);
        cudaEventCreateWithFlags(&evG2a,  cudaEventDisableTiming);
        cudaEventCreateWithFlags(&evE2a,  cudaEventDisableTiming);
        cudaEventCreateWithFlags(&evP1a,  cudaEventDisableTiming);
    }

    const int EDGE_THREADS = 256;
    dim3 ggridF(4, N_PAD / GBM);          // full: 4 x 157
    dim3 ggridA(4, SPLIT_TILES);          // rows [0, 10112)
    dim3 ggridB(4, N_PAD / GBM - SPLIT_TILES);   // rows [10112, 20096)

    // ---- fork side stream: CSR chain + Wt1/Wt2 prep ----
    cudaEventRecord(evFork, 0);
    cudaStreamWaitEvent(s2, evFork, 0);
    initcnt_kernel<<<NBLK_SCAN, 256, 0, s2>>>();
    hist_kernel<<<(N_EDGES / 4 + 255) / 256, 256, 0, s2>>>(dst);
    scanfill_kernel<<<NBLK_SCAN, 256, 0, s2>>>();
    scatter_kernel<<<(N_EDGES / 4 + 255) / 256, 256, 0, s2>>>(src, dst);
    cudaEventRecord(evCsr, s2);
    prep12_kernel<<<(2 * L12_ELEMS) / 256, 256, 0, s2>>>(Wl[1], Wr[1], Wl[2], Wr[2]);
    cudaEventRecord(evPrep, s2);

    // ---- main: Wt0 prep + input proj -> GEMM-0 (full) ----
    fused_init_kernel<<<INIT_BLOCKS, 256>>>(x, Win, bin, Wl[0], Wr[0]);
    gemm_f16_kernel<<<ggridF, 256, GEMM_SMEM>>>(hA, Wt0, xlr, C_DIM, 0);

    // ---- layer 0 edges (need CSR) ----
    cudaStreamWaitEvent(0, evCsr, 0);
    gat_edge_kernel<<<EA_BLOCKS, EDGE_THREADS>>>(xlr, At[0], Bi[0], hA, hB, 0, 0, SPLIT_NODES);
    cudaEventRecord(evE0a, 0);
    gat_edge_kernel<<<EB_BLOCKS, EDGE_THREADS>>>(xlr, At[0], Bi[0], hA, hB, 0, SPLIT_NODES, EB_NODES);

    // ---- layer 1: gemm1_a on s2 overlaps edge0_b ----
    cudaStreamWaitEvent(s2, evE0a, 0);
    gemm_f16_kernel<<<ggridA, 256, GEMM_SMEM, s2>>>(hB, Wt1, xlr, HC, 0);
    cudaEventRecord(evG1a, s2);

    cudaStreamWaitEvent(0, evPrep, 0);
    gemm_f16_kernel<<<ggridB, 256, GEMM_SMEM>>>(hB, Wt1, xlr, HC, SPLIT_TILES);
    cudaStreamWaitEvent(0, evG1a, 0);
    gat_edge_kernel<<<EA_BLOCKS, EDGE_THREADS>>>(xlr, At[1], Bi[1], hB, hA, 1, 0, SPLIT_NODES);
    cudaEventRecord(evE1a, 0);
    gat_edge_kernel<<<EB_BLOCKS, EDGE_THREADS>>>(xlr, At[1], Bi[1], hB, hA, 1, SPLIT_NODES, EB_NODES);

    // ---- layer 2: gemm2_a on s2 overlaps edge1_b ----
    cudaStreamWaitEvent(s2, evE1a, 0);
    gemm_f16_kernel<<<ggridA, 256, GEMM_SMEM, s2>>>(hA, Wt2, xlr, HC, 0);
    cudaEventRecord(evG2a, s2);

    gemm_f16_kernel<<<ggridB, 256, GEMM_SMEM>>>(hA, Wt2, xlr, HC, SPLIT_TILES);
    cudaStreamWaitEvent(0, evG2a, 0);
    gat_edge_kernel<<<EA_BLOCKS, EDGE_THREADS>>>(xlr, At[2], Bi[2], hA, hB, 1, 0, SPLIT_NODES);
    cudaEventRecord(evE2a, 0);
    gat_edge_kernel<<<EB_BLOCKS, EDGE_THREADS>>>(xlr, At[2], Bi[2], hA, hB, 1, SPLIT_NODES, EB_NODES);

    // ---- pooling: graphs 0-9 on s2 overlap edge2_b ----
    cudaStreamWaitEvent(s2, evE2a, 0);
    pool1_kernel<<<dim3(8, 10), HC, 0, s2>>>(hB, 0);
    cudaEventRecord(evP1a, s2);

    pool1_kernel<<<dim3(8, 10), HC>>>(hB, 10);
    cudaStreamWaitEvent(0, evP1a, 0);
    pool2_head_kernel<<<G_GRAPHS, HC>>>(Wout, bout, out);
}